// round 11
// baseline (speedup 1.0000x reference)
#include <cuda_runtime.h>
#include <cuda_bf16.h>
#include <math.h>
#include <stdint.h>

// ---------------------------------------------------------------------------
// Problem constants
// ---------------------------------------------------------------------------
#define NPOS   32768          // 32*32*32
#define CCH    128
#define NHEADS 8
#define FFN    512

// Scratch (device globals; allocation-free)
__device__ float g_qkv [NPOS * 384];                              // 48 MB fp32 qkv
__device__ float g_proj[NPOS * CCH];                              // 16 MB
__device__ float g_y   [NPOS * CCH];                              // 16 MB
__device__ __nv_bfloat16 g_xh [NPOS * CCH], g_xl [NPOS * CCH];    // x^T split
__device__ __nv_bfloat16 g_ath[NPOS * CCH], g_atl[NPOS * CCH];    // attn out split
__device__ __nv_bfloat16 g_ph [NPOS * CCH], g_pl [NPOS * CCH];    // norm(proj) split
__device__ __nv_bfloat16 g_f1h[NPOS * FFN], g_f1l[NPOS * FFN];    // ffn1 out split
__device__ __nv_bfloat16 g_wh [196608], g_wl [196608];            // weights split
__device__ float g_part [2 * 256 * 128];
__device__ float g_stats[256];          // [mean | rstd]

#define WT_QKV  0
#define WT_PROJ 49152
#define WT_FFN1 65536
#define WT_FFN2 131072

// ---------------------------------------------------------------------------
// PTX helpers
// ---------------------------------------------------------------------------
__device__ __forceinline__ uint32_t smem_u32(const void* p) {
    uint32_t a;
    asm("{ .reg .u64 t; cvta.to.shared.u64 t, %1; cvt.u32.u64 %0, t; }" : "=r"(a) : "l"(p));
    return a;
}
__device__ __forceinline__ float fast_tanh(float x) {
    float r; asm("tanh.approx.f32 %0, %1;" : "=f"(r) : "f"(x)); return r;
}
__device__ __forceinline__ void ldsm_x4(uint32_t* r, uint32_t addr) {
    asm volatile("ldmatrix.sync.aligned.m8n8.x4.shared.b16 {%0,%1,%2,%3}, [%4];"
        : "=r"(r[0]), "=r"(r[1]), "=r"(r[2]), "=r"(r[3]) : "r"(addr));
}
__device__ __forceinline__ void ldsm_x4_t(uint32_t* r, uint32_t addr) {
    asm volatile("ldmatrix.sync.aligned.m8n8.x4.trans.shared.b16 {%0,%1,%2,%3}, [%4];"
        : "=r"(r[0]), "=r"(r[1]), "=r"(r[2]), "=r"(r[3]) : "r"(addr));
}
__device__ __forceinline__ void mma16816(float* c, const uint32_t* a, const uint32_t* b) {
    asm volatile("mma.sync.aligned.m16n8k16.row.col.f32.bf16.bf16.f32 "
        "{%0,%1,%2,%3}, {%4,%5,%6,%7}, {%8,%9}, {%0,%1,%2,%3};"
        : "+f"(c[0]), "+f"(c[1]), "+f"(c[2]), "+f"(c[3])
        : "r"(a[0]), "r"(a[1]), "r"(a[2]), "r"(a[3]), "r"(b[0]), "r"(b[1]));
}
__device__ __forceinline__ void split_bf16(float v, __nv_bfloat16& h, __nv_bfloat16& l) {
    h = __float2bfloat16(v);
    l = __float2bfloat16(v - __bfloat162float(h));
}

// ---------------------------------------------------------------------------
// Prep kernels
// ---------------------------------------------------------------------------
__global__ void splitw(const float* __restrict__ wqkv, const float* __restrict__ wproj,
                       const float* __restrict__ wf1, const float* __restrict__ wf2,
                       __nv_bfloat16* __restrict__ wh, __nv_bfloat16* __restrict__ wl)
{
    int i = blockIdx.x * blockDim.x + threadIdx.x;
    if (i >= 196608) return;
    float v;
    if (i < 49152)       v = wqkv[i];
    else if (i < 65536)  v = wproj[i - 49152];
    else if (i < 131072) v = wf1[i - 65536];
    else                 v = wf2[i - 131072];
    __nv_bfloat16 h, l;
    split_bf16(v, h, l);
    wh[i] = h; wl[i] = l;
}

// transpose + split x: [128][NPOS] -> xh/xl [NPOS][128]
__global__ __launch_bounds__(256)
void splitx(const float* __restrict__ x,
            __nv_bfloat16* __restrict__ xh, __nv_bfloat16* __restrict__ xl)
{
    __shared__ float tile[32][33];
    const int n0 = blockIdx.x * 32;
    const int c0 = blockIdx.y * 32;
    const int tx = threadIdx.x, ty = threadIdx.y;
    for (int i = ty; i < 32; i += 8)
        tile[i][tx] = x[(size_t)(c0 + i) * NPOS + n0 + tx];
    __syncthreads();
    for (int i = ty; i < 32; i += 8) {
        float v = tile[tx][i];
        __nv_bfloat16 h, l;
        split_bf16(v, h, l);
        size_t o = (size_t)(n0 + i) * 128 + c0 + tx;
        xh[o] = h; xl[o] = l;
    }
}

// normalize proj and split to ph/pl
__global__ __launch_bounds__(256)
void normsplit(const float* __restrict__ proj, const float* __restrict__ st,
               __nv_bfloat16* __restrict__ ph, __nv_bfloat16* __restrict__ pl)
{
    int i = blockIdx.x * blockDim.x + threadIdx.x;       // over NPOS*32 float4s
    const float4 v4 = reinterpret_cast<const float4*>(proj)[i];
    int c4 = (i & 31) * 4;
    float vals[4] = {v4.x, v4.y, v4.z, v4.w};
    uint32_t hp[2], lp[2];
    #pragma unroll
    for (int p = 0; p < 2; p++) {
        __nv_bfloat16 h0, l0, h1, l1;
        split_bf16((vals[2*p]   - st[c4+2*p])   * st[128 + c4+2*p],   h0, l0);
        split_bf16((vals[2*p+1] - st[c4+2*p+1]) * st[128 + c4+2*p+1], h1, l1);
        __nv_bfloat162 hh(h0, h1), ll(l0, l1);
        hp[p] = *reinterpret_cast<uint32_t*>(&hh);
        lp[p] = *reinterpret_cast<uint32_t*>(&ll);
    }
    *reinterpret_cast<uint2*>(&ph[(size_t)i * 4]) = make_uint2(hp[0], hp[1]);
    *reinterpret_cast<uint2*>(&pl[(size_t)i * 4]) = make_uint2(lp[0], lp[1]);
}

// ---------------------------------------------------------------------------
// Split-bf16 GEMM: compute core byte-identical to R7; fills are pure copies
// of pre-split operands. C[M,J] = act( A @ W^T + bias ).
//   GELU  : gelu on output
//   RESID : out += resid_h + resid_l
//   OSPLIT: write output as bf16 hi/lo pair instead of fp32
// ---------------------------------------------------------------------------
#define APAD 8
#define BPAD 8

template<bool GELU, bool RESID, bool OSPLIT>
__global__ __launch_bounds__(256)
void mmagemm(const __nv_bfloat16* __restrict__ Ah, const __nv_bfloat16* __restrict__ Al,
             const __nv_bfloat16* __restrict__ Wh, const __nv_bfloat16* __restrict__ Wl,
             const float* __restrict__ bias,
             const __nv_bfloat16* __restrict__ resid_h, const __nv_bfloat16* __restrict__ resid_l,
             float* __restrict__ Cf,
             __nv_bfloat16* __restrict__ Ch, __nv_bfloat16* __restrict__ Cl,
             int M, int J, int Kd)
{
    __shared__ __nv_bfloat16 As_h[128][32 + APAD];
    __shared__ __nv_bfloat16 As_l[128][32 + APAD];
    __shared__ __nv_bfloat16 Bs_h[32][128 + BPAD];
    __shared__ __nv_bfloat16 Bs_l[32][128 + BPAD];

    const int tid  = threadIdx.x;
    const int wid  = tid >> 5;
    const int lane = tid & 31;
    const int m0 = blockIdx.y * 128;
    const int j0 = blockIdx.x * 128;
    const int mw = wid >> 2;       // 0-1
    const int nw = wid & 3;        // 0-3

    const uint32_t sAh = smem_u32(As_h), sAl = smem_u32(As_l);
    const uint32_t sBh = smem_u32(Bs_h), sBl = smem_u32(Bs_l);

    float acc[4][4][4] = {};       // [mt][nt][frag]

    const int nchunk = Kd >> 5;
    for (int kc = 0; kc < nchunk; kc++) {
        const int k0 = kc << 5;

        // ---- fill A (pure copy of pre-split rows) ----
        #pragma unroll
        for (int it = 0; it < 2; it++) {
            const int idx = tid + it * 256;       // 512 = 128 rows x 4 groups
            int r  = idx >> 2;
            int c8 = (idx & 3) << 3;
            *reinterpret_cast<uint4*>(&As_h[r][c8]) =
                *reinterpret_cast<const uint4*>(&Ah[(size_t)(m0 + r) * Kd + k0 + c8]);
            *reinterpret_cast<uint4*>(&As_l[r][c8]) =
                *reinterpret_cast<const uint4*>(&Al[(size_t)(m0 + r) * Kd + k0 + c8]);
        }
        // ---- fill B (pre-split [J][Kd] rows; store k-major as in R7) ----
        #pragma unroll
        for (int it = 0; it < 2; it++) {
            const int idx = tid + it * 256;       // 512 = 128 j x 4 kgroups
            int n  = idx & 127;
            int kg = (idx >> 7) << 3;
            uint4 vh = *reinterpret_cast<const uint4*>(&Wh[(size_t)(j0 + n) * Kd + k0 + kg]);
            uint4 vl = *reinterpret_cast<const uint4*>(&Wl[(size_t)(j0 + n) * Kd + k0 + kg]);
            const __nv_bfloat16* hp = reinterpret_cast<const __nv_bfloat16*>(&vh);
            const __nv_bfloat16* lp = reinterpret_cast<const __nv_bfloat16*>(&vl);
            #pragma unroll
            for (int e = 0; e < 8; e++) {
                Bs_h[kg + e][n] = hp[e];
                Bs_l[kg + e][n] = lp[e];
            }
        }
        __syncthreads();

        // ---- 2 k-steps of 16 (identical to R7) ----
        #pragma unroll
        for (int ks = 0; ks < 2; ks++) {
            const int k16 = ks << 4;
            const int arow = mw * 64 + (lane & 15);
            const int acol = k16 + ((lane >> 4) << 3);
            uint32_t ah[4][4], al[4][4], bh[4][2], bl[4][2];
            #pragma unroll
            for (int mt = 0; mt < 4; mt++) {
                uint32_t aoff = (uint32_t)((arow + mt * 16) * (32 + APAD) + acol) * 2u;
                ldsm_x4(ah[mt], sAh + aoff);
                ldsm_x4(al[mt], sAl + aoff);
            }
            const int brow = k16 + (lane & 15);
            #pragma unroll
            for (int half = 0; half < 2; half++) {
                uint32_t boff = (uint32_t)(brow * (128 + BPAD)
                              + nw * 32 + half * 16 + ((lane >> 4) << 3)) * 2u;
                uint32_t t[4];
                ldsm_x4_t(t, sBh + boff);
                bh[half*2][0] = t[0]; bh[half*2][1] = t[1];
                bh[half*2+1][0] = t[2]; bh[half*2+1][1] = t[3];
                ldsm_x4_t(t, sBl + boff);
                bl[half*2][0] = t[0]; bl[half*2][1] = t[1];
                bl[half*2+1][0] = t[2]; bl[half*2+1][1] = t[3];
            }
            #pragma unroll
            for (int mt = 0; mt < 4; mt++)
                #pragma unroll
                for (int nt = 0; nt < 4; nt++) {
                    mma16816(acc[mt][nt], ah[mt], bh[nt]);
                    mma16816(acc[mt][nt], ah[mt], bl[nt]);
                    mma16816(acc[mt][nt], al[mt], bh[nt]);
                }
        }
        __syncthreads();
    }

    // ---- epilogue ----
    #pragma unroll
    for (int mt = 0; mt < 4; mt++) {
        #pragma unroll
        for (int nt = 0; nt < 4; nt++) {
            int mrow = m0 + mw * 64 + mt * 16 + (lane >> 2);
            int col  = j0 + nw * 32 + nt * 8 + (lane & 3) * 2;
            #pragma unroll
            for (int hh = 0; hh < 2; hh++) {
                int m = mrow + hh * 8;
                float v0 = acc[mt][nt][hh*2]   + bias[col];
                float v1 = acc[mt][nt][hh*2+1] + bias[col + 1];
                if (GELU) {
                    float t0 = fast_tanh(0.7978845608028654f * (v0 + 0.044715f * v0 * v0 * v0));
                    v0 = 0.5f * v0 * (1.0f + t0);
                    float t1 = fast_tanh(0.7978845608028654f * (v1 + 0.044715f * v1 * v1 * v1));
                    v1 = 0.5f * v1 * (1.0f + t1);
                }
                if (RESID) {
                    __nv_bfloat162 rh = *reinterpret_cast<const __nv_bfloat162*>(&resid_h[(size_t)m * J + col]);
                    __nv_bfloat162 rl = *reinterpret_cast<const __nv_bfloat162*>(&resid_l[(size_t)m * J + col]);
                    v0 += __bfloat162float(rh.x) + __bfloat162float(rl.x);
                    v1 += __bfloat162float(rh.y) + __bfloat162float(rl.y);
                }
                if (OSPLIT) {
                    __nv_bfloat16 h0, l0, h1, l1;
                    split_bf16(v0, h0, l0);
                    split_bf16(v1, h1, l1);
                    *reinterpret_cast<__nv_bfloat162*>(&Ch[(size_t)m * J + col]) = __nv_bfloat162(h0, h1);
                    *reinterpret_cast<__nv_bfloat162*>(&Cl[(size_t)m * J + col]) = __nv_bfloat162(l0, l1);
                } else {
                    *reinterpret_cast<float2*>(&Cf[(size_t)m * J + col]) = make_float2(v0, v1);
                }
            }
        }
    }
}

// ---------------------------------------------------------------------------
// Neighborhood attention: block = 4x4x8 tile x one head, 128 threads.
// XOR-swizzled K/V staging (R7); output written pre-split (hi/lo bf16).
// ---------------------------------------------------------------------------
__global__ __launch_bounds__(128)
void nattn(const float* __restrict__ qkv, const float* __restrict__ rpb,
           __nv_bfloat16* __restrict__ oh, __nv_bfloat16* __restrict__ ol)
{
    __shared__ float Kt[360 * 16];
    __shared__ float Vt[360 * 16];
    __shared__ float Bsh[125];

    const int head = blockIdx.y;
    const int tile = blockIdx.x;                 // 256 tiles: th(8) tw(8) tz(4)
    const int th = tile >> 5, tw = (tile >> 2) & 7, tz = tile & 3;
    const int h0 = th * 4, w0 = tw * 4, z0 = tz * 8;
    const int rbh = h0 - 1, rbw = w0 - 1, rbz = z0 - 1;
    const int tid = threadIdx.x;

    for (int i = tid; i < 360 * 4; i += 128) {
        int p = i >> 2, j = i & 3;
        int pz = p % 10, pr = p / 10;
        int pw = pr % 6, ph = pr / 6;
        int gh = min(max(rbh + ph, 0), 31);
        int gw = min(max(rbw + pw, 0), 31);
        int gz = min(max(rbz + pz, 0), 31);
        int n = (gh * 32 + gw) * 32 + gz;
        const float* base = qkv + (size_t)n * 384 + 128 + head * 16 + j * 4;
        int s = (p * 4 + (j ^ ((p >> 1) & 3))) * 4;
        *reinterpret_cast<float4*>(&Kt[s]) = *reinterpret_cast<const float4*>(base);
        *reinterpret_cast<float4*>(&Vt[s]) = *reinterpret_cast<const float4*>(base + 128);
    }
    for (int i = tid; i < 125; i += 128) Bsh[i] = rpb[head * 125 + i];
    __syncthreads();

    const int lz = tid & 7, lw = (tid >> 3) & 3, lh = tid >> 5;
    const int qh = h0 + lh, qw = w0 + lw, qz = z0 + lz;
    const int n = (qh * 32 + qw) * 32 + qz;

    float q[16];
    {
        const float4* qp = reinterpret_cast<const float4*>(qkv + (size_t)n * 384 + head * 16);
        #pragma unroll
        for (int d4 = 0; d4 < 4; d4++) {
            float4 v = qp[d4];
            q[d4*4+0] = v.x * 0.25f; q[d4*4+1] = v.y * 0.25f;
            q[d4*4+2] = v.z * 0.25f; q[d4*4+3] = v.w * 0.25f;
        }
    }

    const int sh = min(max(qh - 1, 0), 29);
    const int sw = min(max(qw - 1, 0), 29);
    const int sz = min(max(qz - 1, 0), 29);

    float logits[27];
    float mx = -1e30f;
    #pragma unroll
    for (int ii = 0; ii < 27; ii++) {
        int iz = ii % 3, iw = (ii / 3) % 3, ih = ii / 9;
        int nh = sh + ih, nw_ = sw + iw, nz = sz + iz;
        int sp = ((nh - rbh) * 6 + (nw_ - rbw)) * 10 + (nz - rbz);
        float dot = 0.f;
        #pragma unroll
        for (int j = 0; j < 4; j++) {
            int s = (sp * 4 + (j ^ ((sp >> 1) & 3))) * 4;
            float4 kv = *reinterpret_cast<const float4*>(&Kt[s]);
            dot += q[j*4+0]*kv.x + q[j*4+1]*kv.y + q[j*4+2]*kv.z + q[j*4+3]*kv.w;
        }
        int rh = nh - qh + 2, rw = nw_ - qw + 2, rz = nz - qz + 2;
        dot += Bsh[(rh * 5 + rw) * 5 + rz];
        logits[ii] = dot;
        mx = fmaxf(mx, dot);
    }
    float s = 0.f;
    #pragma unroll
    for (int ii = 0; ii < 27; ii++) { logits[ii] = __expf(logits[ii] - mx); s += logits[ii]; }
    const float inv = 1.0f / s;

    float o[16] = {};
    #pragma unroll
    for (int ii = 0; ii < 27; ii++) {
        int iz = ii % 3, iw = (ii / 3) % 3, ih = ii / 9;
        int sp = ((sh + ih - rbh) * 6 + (sw + iw - rbw)) * 10 + (sz + iz - rbz);
        float w = logits[ii];
        #pragma unroll
        for (int j = 0; j < 4; j++) {
            int sidx = (sp * 4 + (j ^ ((sp >> 1) & 3))) * 4;
            float4 vv = *reinterpret_cast<const float4*>(&Vt[sidx]);
            o[j*4+0] += w * vv.x; o[j*4+1] += w * vv.y;
            o[j*4+2] += w * vv.z; o[j*4+3] += w * vv.w;
        }
    }
    const size_t ob = (size_t)n * 128 + head * 16;
    #pragma unroll
    for (int d2 = 0; d2 < 8; d2++) {
        float v0 = o[d2*2]   * inv;
        float v1 = o[d2*2+1] * inv;
        __nv_bfloat16 h0, l0, h1, l1;
        split_bf16(v0, h0, l0);
        split_bf16(v1, h1, l1);
        *reinterpret_cast<__nv_bfloat162*>(&oh[ob + d2*2]) = __nv_bfloat162(h0, h1);
        *reinterpret_cast<__nv_bfloat162*>(&ol[ob + d2*2]) = __nv_bfloat162(l0, l1);
    }
}

// ---------------------------------------------------------------------------
// Instance-norm stats (R9-proven): 256 blocks x 256 threads, float4 loads.
// ---------------------------------------------------------------------------
__global__ __launch_bounds__(256)
void stats_kernel(const float* __restrict__ y, float* __restrict__ part)
{
    __shared__ float sS[8][128];
    __shared__ float sS2[8][128];

    const int tid = threadIdx.x;
    const int c4  = (tid & 31) * 4;
    const int rg  = tid >> 5;
    const int r0  = blockIdx.x * 128;

    float s[4] = {}, s2[4] = {};
    #pragma unroll 16
    for (int r = rg; r < 128; r += 8) {
        float4 v = *reinterpret_cast<const float4*>(&y[(size_t)(r0 + r) * 128 + c4]);
        s[0] += v.x; s2[0] += v.x * v.x;
        s[1] += v.y; s2[1] += v.y * v.y;
        s[2] += v.z; s2[2] += v.z * v.z;
        s[3] += v.w; s2[3] += v.w * v.w;
    }
    #pragma unroll
    for (int e = 0; e < 4; e++) { sS[rg][c4 + e] = s[e]; sS2[rg][c4 + e] = s2[e]; }
    __syncthreads();
    if (tid < 128) {
        float ts = 0.f, ts2 = 0.f;
        #pragma unroll
        for (int g = 0; g < 8; g++) { ts += sS[g][tid]; ts2 += sS2[g][tid]; }
        part[blockIdx.x * 128 + tid] = ts;
        part[256 * 128 + blockIdx.x * 128 + tid] = ts2;
    }
}

__global__ void finalize_stats(const float* __restrict__ part, float* __restrict__ st)
{
    int c = threadIdx.x;
    float s = 0.f, s2 = 0.f;
    for (int b = 0; b < 256; b++) {
        s  += part[b * 128 + c];
        s2 += part[256 * 128 + b * 128 + c];
    }
    float m = s * (1.0f / NPOS);
    st[c] = m;
    st[128 + c] = rsqrtf(s2 * (1.0f / NPOS) - m * m + 1e-5f);
}

// ---------------------------------------------------------------------------
// Final: normalize + transpose [N,128] -> [128,N]
// ---------------------------------------------------------------------------
__global__ __launch_bounds__(256)
void transnorm(const float* __restrict__ y, const float* __restrict__ st,
               float* __restrict__ out)
{
    __shared__ float tile[32][33];
    const int n0 = blockIdx.x * 32;
    const int c0 = blockIdx.y * 32;
    const int tx = threadIdx.x, ty = threadIdx.y;
    for (int i = ty; i < 32; i += 8)
        tile[i][tx] = y[(size_t)(n0 + i) * 128 + c0 + tx];
    __syncthreads();
    for (int i = ty; i < 32; i += 8) {
        int c = c0 + i;
        out[(size_t)c * NPOS + n0 + tx] = (tile[tx][i] - st[c]) * st[128 + c];
    }
}

// ---------------------------------------------------------------------------
// Launch
// ---------------------------------------------------------------------------
extern "C" void kernel_launch(void* const* d_in, const int* in_sizes, int n_in,
                              void* d_out, int out_size)
{
    const float* x      = (const float*)d_in[0];
    const float* w_qkv  = (const float*)d_in[1];
    const float* b_qkv  = (const float*)d_in[2];
    const float* rpb    = (const float*)d_in[3];
    const float* w_proj = (const float*)d_in[4];
    const float* b_proj = (const float*)d_in[5];
    const float* w_ffn1 = (const float*)d_in[6];
    const float* b_ffn1 = (const float*)d_in[7];
    const float* w_ffn2 = (const float*)d_in[8];
    const float* b_ffn2 = (const float*)d_in[9];
    float* out = (float*)d_out;

    float *qkv, *proj, *y, *part, *st;
    __nv_bfloat16 *xh, *xl, *ath, *atl, *ph, *pl, *f1h, *f1l, *wh, *wl;
    cudaGetSymbolAddress((void**)&qkv,  g_qkv);
    cudaGetSymbolAddress((void**)&proj, g_proj);
    cudaGetSymbolAddress((void**)&y,    g_y);
    cudaGetSymbolAddress((void**)&part, g_part);
    cudaGetSymbolAddress((void**)&st,   g_stats);
    cudaGetSymbolAddress((void**)&xh,   g_xh);
    cudaGetSymbolAddress((void**)&xl,   g_xl);
    cudaGetSymbolAddress((void**)&ath,  g_ath);
    cudaGetSymbolAddress((void**)&atl,  g_atl);
    cudaGetSymbolAddress((void**)&ph,   g_ph);
    cudaGetSymbolAddress((void**)&pl,   g_pl);
    cudaGetSymbolAddress((void**)&f1h,  g_f1h);
    cudaGetSymbolAddress((void**)&f1l,  g_f1l);
    cudaGetSymbolAddress((void**)&wh,   g_wh);
    cudaGetSymbolAddress((void**)&wl,   g_wl);

    // 1. split weights; split/transpose x
    splitw<<<768, 256>>>(w_qkv, w_proj, w_ffn1, w_ffn2, wh, wl);
    splitx<<<dim3(1024, 4), dim3(32, 8)>>>(x, xh, xl);

    // 2. QKV GEMM (A = pre-split x^T) -> qkv fp32
    mmagemm<false,false,false><<<dim3(3, 256), 256>>>(
        xh, xl, wh + WT_QKV, wl + WT_QKV, b_qkv,
        nullptr, nullptr, qkv, nullptr, nullptr, NPOS, 384, 128);

    // 3. neighborhood attention -> split output
    nattn<<<dim3(256, NHEADS), 128>>>(qkv, rpb, ath, atl);

    // 4. proj GEMM (A = split attn out) -> proj fp32
    mmagemm<false,false,false><<<dim3(1, 256), 256>>>(
        ath, atl, wh + WT_PROJ, wl + WT_PROJ, b_proj,
        nullptr, nullptr, proj, nullptr, nullptr, NPOS, 128, 128);

    // 5. instance norm #1 stats; normalize+split proj
    stats_kernel<<<256, 256>>>(proj, part);
    finalize_stats<<<1, 128>>>(part, st);
    normsplit<<<4096, 256>>>(proj, st, ph, pl);

    // 6. FFN1 (A = norm proj split) + gelu -> split output
    mmagemm<true,false,true><<<dim3(4, 256), 256>>>(
        ph, pl, wh + WT_FFN1, wl + WT_FFN1, b_ffn1,
        nullptr, nullptr, nullptr, f1h, f1l, NPOS, 512, 128);

    // 7. FFN2 (A = ffn1 split) + residual -> y fp32
    mmagemm<false,true,false><<<dim3(1, 256), 256>>>(
        f1h, f1l, wh + WT_FFN2, wl + WT_FFN2, b_ffn2,
        ph, pl, y, nullptr, nullptr, NPOS, 128, 512);

    // 8. instance norm #2 stats
    stats_kernel<<<256, 256>>>(y, part);
    finalize_stats<<<1, 128>>>(part, st);

    // 9. normalize + transpose to [C, N]
    transnorm<<<dim3(1024, 4), dim3(32, 8)>>>(y, st, out);
}

// round 15
// speedup vs baseline: 1.0905x; 1.0905x over previous
#include <cuda_runtime.h>
#include <cuda_bf16.h>
#include <math.h>
#include <stdint.h>

// ---------------------------------------------------------------------------
// Problem constants
// ---------------------------------------------------------------------------
#define NPOS   32768          // 32*32*32
#define CCH    128
#define NHEADS 8
#define FFN    512

// Scratch (device globals; allocation-free)
__device__ float g_qkv  [NPOS * 384];   // 48 MB
__device__ float g_attno[NPOS * CCH];   // 16 MB
__device__ float g_proj [NPOS * CCH];   // 16 MB
__device__ float g_ffn1 [NPOS * FFN];   // 64 MB
__device__ float g_y    [NPOS * CCH];   // 16 MB
__device__ float g_part [2 * 256 * 128]; // per-block stat partials
__device__ float g_stats[256];          // [mean | rstd]

// ---------------------------------------------------------------------------
// PTX helpers (family-portable: ldmatrix + mma.sync, sm_80+ baseline)
// ---------------------------------------------------------------------------
__device__ __forceinline__ uint32_t smem_u32(const void* p) {
    uint32_t a;
    asm("{ .reg .u64 t; cvta.to.shared.u64 t, %1; cvt.u32.u64 %0, t; }" : "=r"(a) : "l"(p));
    return a;
}
__device__ __forceinline__ float fast_tanh(float x) {
    float r; asm("tanh.approx.f32 %0, %1;" : "=f"(r) : "f"(x)); return r;
}
__device__ __forceinline__ void ldsm_x4(uint32_t* r, uint32_t addr) {
    asm volatile("ldmatrix.sync.aligned.m8n8.x4.shared.b16 {%0,%1,%2,%3}, [%4];"
        : "=r"(r[0]), "=r"(r[1]), "=r"(r[2]), "=r"(r[3]) : "r"(addr));
}
__device__ __forceinline__ void ldsm_x4_t(uint32_t* r, uint32_t addr) {
    asm volatile("ldmatrix.sync.aligned.m8n8.x4.trans.shared.b16 {%0,%1,%2,%3}, [%4];"
        : "=r"(r[0]), "=r"(r[1]), "=r"(r[2]), "=r"(r[3]) : "r"(addr));
}
__device__ __forceinline__ void mma16816(float* c, const uint32_t* a, const uint32_t* b) {
    asm volatile("mma.sync.aligned.m16n8k16.row.col.f32.bf16.bf16.f32 "
        "{%0,%1,%2,%3}, {%4,%5,%6,%7}, {%8,%9}, {%0,%1,%2,%3};"
        : "+f"(c[0]), "+f"(c[1]), "+f"(c[2]), "+f"(c[3])
        : "r"(a[0]), "r"(a[1]), "r"(a[2]), "r"(a[3]), "r"(b[0]), "r"(b[1]));
}

// ---------------------------------------------------------------------------
// Split-bf16 GEMM on mma.sync tensor cores (R7/R9-proven version).
// ---------------------------------------------------------------------------
#define APAD 8
#define BPAD 8

template<bool ATRANS, bool ANORM, bool GELU, bool RESID>
__global__ __launch_bounds__(256)
void mmagemm(const float* __restrict__ A, const float* __restrict__ W,
             const float* __restrict__ bias,
             const float* __restrict__ nmean, const float* __restrict__ nrstd,
             const float* __restrict__ resid,
             float* __restrict__ C, int M, int J, int Kd)
{
    __shared__ __nv_bfloat16 As_h[128][32 + APAD];
    __shared__ __nv_bfloat16 As_l[128][32 + APAD];
    __shared__ __nv_bfloat16 Bs_h[32][128 + BPAD];
    __shared__ __nv_bfloat16 Bs_l[32][128 + BPAD];

    const int tid  = threadIdx.x;
    const int wid  = tid >> 5;
    const int lane = tid & 31;
    const int m0 = blockIdx.y * 128;
    const int j0 = blockIdx.x * 128;
    const int mw = wid >> 2;       // 0-1
    const int nw = wid & 3;        // 0-3

    const uint32_t sAh = smem_u32(As_h), sAl = smem_u32(As_l);
    const uint32_t sBh = smem_u32(Bs_h), sBl = smem_u32(Bs_l);

    float acc[4][4][4] = {};       // [mt][nt][frag]

    const int nchunk = Kd >> 5;
    for (int kc = 0; kc < nchunk; kc++) {
        const int k0 = kc << 5;

        // ---- fill A hi/lo ----
        if (ATRANS) {
            #pragma unroll
            for (int idx = tid; idx < 1024; idx += 256) {
                int k  = idx >> 5;
                int m4 = (idx & 31) << 2;
                float4 v = *reinterpret_cast<const float4*>(&A[(size_t)(k0 + k) * M + m0 + m4]);
                float vals[4] = {v.x, v.y, v.z, v.w};
                #pragma unroll
                for (int e = 0; e < 4; e++) {
                    __nv_bfloat16 h = __float2bfloat16(vals[e]);
                    __nv_bfloat16 l = __float2bfloat16(vals[e] - __bfloat162float(h));
                    As_h[m4 + e][k] = h;
                    As_l[m4 + e][k] = l;
                }
            }
        } else {
            #pragma unroll
            for (int idx = tid; idx < 1024; idx += 256) {
                int r  = idx >> 3;
                int c4 = (idx & 7) << 2;
                float4 v = *reinterpret_cast<const float4*>(&A[(size_t)(m0 + r) * Kd + k0 + c4]);
                float vals[4] = {v.x, v.y, v.z, v.w};
                if (ANORM) {
                    #pragma unroll
                    for (int e = 0; e < 4; e++) {
                        int kk = k0 + c4 + e;
                        vals[e] = (vals[e] - nmean[kk]) * nrstd[kk];
                    }
                }
                #pragma unroll
                for (int e = 0; e < 2; e++) {
                    __nv_bfloat16 h0 = __float2bfloat16(vals[2*e]);
                    __nv_bfloat16 h1 = __float2bfloat16(vals[2*e+1]);
                    __nv_bfloat16 l0 = __float2bfloat16(vals[2*e]   - __bfloat162float(h0));
                    __nv_bfloat16 l1 = __float2bfloat16(vals[2*e+1] - __bfloat162float(h1));
                    *reinterpret_cast<__nv_bfloat162*>(&As_h[r][c4 + 2*e]) = __nv_bfloat162(h0, h1);
                    *reinterpret_cast<__nv_bfloat162*>(&As_l[r][c4 + 2*e]) = __nv_bfloat162(l0, l1);
                }
            }
        }
        // ---- fill B hi/lo (W is [J, Kd] row-major; store k-major) ----
        #pragma unroll
        for (int idx = tid; idx < 1024; idx += 256) {
            int n  = idx >> 3;
            int kg = (idx & 7) << 2;
            float4 v = *reinterpret_cast<const float4*>(&W[(size_t)(j0 + n) * Kd + k0 + kg]);
            float vals[4] = {v.x, v.y, v.z, v.w};
            #pragma unroll
            for (int e = 0; e < 4; e++) {
                __nv_bfloat16 h = __float2bfloat16(vals[e]);
                __nv_bfloat16 l = __float2bfloat16(vals[e] - __bfloat162float(h));
                Bs_h[kg + e][n] = h;
                Bs_l[kg + e][n] = l;
            }
        }
        __syncthreads();

        // ---- 2 k-steps of 16 ----
        #pragma unroll
        for (int ks = 0; ks < 2; ks++) {
            const int k16 = ks << 4;
            const int arow = mw * 64 + (lane & 15);
            const int acol = k16 + ((lane >> 4) << 3);
            uint32_t ah[4][4], al[4][4], bh[4][2], bl[4][2];
            #pragma unroll
            for (int mt = 0; mt < 4; mt++) {
                uint32_t aoff = (uint32_t)((arow + mt * 16) * (32 + APAD) + acol) * 2u;
                ldsm_x4(ah[mt], sAh + aoff);
                ldsm_x4(al[mt], sAl + aoff);
            }
            const int brow = k16 + (lane & 15);
            #pragma unroll
            for (int half = 0; half < 2; half++) {
                uint32_t boff = (uint32_t)(brow * (128 + BPAD)
                              + nw * 32 + half * 16 + ((lane >> 4) << 3)) * 2u;
                uint32_t t[4];
                ldsm_x4_t(t, sBh + boff);
                bh[half*2][0] = t[0]; bh[half*2][1] = t[1];
                bh[half*2+1][0] = t[2]; bh[half*2+1][1] = t[3];
                ldsm_x4_t(t, sBl + boff);
                bl[half*2][0] = t[0]; bl[half*2][1] = t[1];
                bl[half*2+1][0] = t[2]; bl[half*2+1][1] = t[3];
            }
            #pragma unroll
            for (int mt = 0; mt < 4; mt++)
                #pragma unroll
                for (int nt = 0; nt < 4; nt++) {
                    mma16816(acc[mt][nt], ah[mt], bh[nt]);
                    mma16816(acc[mt][nt], ah[mt], bl[nt]);
                    mma16816(acc[mt][nt], al[mt], bh[nt]);
                }
        }
        __syncthreads();
    }

    // ---- epilogue ----
    #pragma unroll
    for (int mt = 0; mt < 4; mt++) {
        #pragma unroll
        for (int nt = 0; nt < 4; nt++) {
            int mrow = m0 + mw * 64 + mt * 16 + (lane >> 2);
            int col  = j0 + nw * 32 + nt * 8 + (lane & 3) * 2;
            #pragma unroll
            for (int hh = 0; hh < 2; hh++) {
                int m = mrow + hh * 8;
                float2 o;
                float vv[2] = {acc[mt][nt][hh*2], acc[mt][nt][hh*2+1]};
                #pragma unroll
                for (int q = 0; q < 2; q++) {
                    int jj = col + q;
                    float v = vv[q] + bias[jj];
                    if (GELU) {
                        float xx = v;
                        float t = fast_tanh(0.7978845608028654f * (xx + 0.044715f * xx * xx * xx));
                        v = 0.5f * xx * (1.0f + t);
                    }
                    if (RESID) {
                        float r = resid[(size_t)m * J + jj];
                        v += (r - nmean[jj]) * nrstd[jj];
                    }
                    (q == 0 ? o.x : o.y) = v;
                }
                *reinterpret_cast<float2*>(&C[(size_t)m * J + col]) = o;
            }
        }
    }
}

// ---------------------------------------------------------------------------
// Neighborhood attention: block = 4x4x8 tile x one head, 128 threads.
// XOR-swizzled conflict-free K/V staging. Single change this round:
// __launch_bounds__(128, 4) caps regs at 128 -> 4 blocks/SM residency.
// ---------------------------------------------------------------------------
__global__ __launch_bounds__(128, 4)
void nattn(const float* __restrict__ qkv, const float* __restrict__ rpb,
           float* __restrict__ out)
{
    __shared__ float Kt[360 * 16];
    __shared__ float Vt[360 * 16];
    __shared__ float Bsh[125];

    const int head = blockIdx.y;
    const int tile = blockIdx.x;                 // 256 tiles: th(8) tw(8) tz(4)
    const int th = tile >> 5, tw = (tile >> 2) & 7, tz = tile & 3;
    const int h0 = th * 4, w0 = tw * 4, z0 = tz * 8;
    const int rbh = h0 - 1, rbw = w0 - 1, rbz = z0 - 1;
    const int tid = threadIdx.x;

    for (int i = tid; i < 360 * 4; i += 128) {
        int p = i >> 2, j = i & 3;
        int pz = p % 10, pr = p / 10;
        int pw = pr % 6, ph = pr / 6;
        int gh = min(max(rbh + ph, 0), 31);
        int gw = min(max(rbw + pw, 0), 31);
        int gz = min(max(rbz + pz, 0), 31);
        int n = (gh * 32 + gw) * 32 + gz;
        const float* base = qkv + (size_t)n * 384 + 128 + head * 16 + j * 4;
        int s = (p * 4 + (j ^ ((p >> 1) & 3))) * 4;
        *reinterpret_cast<float4*>(&Kt[s]) = *reinterpret_cast<const float4*>(base);
        *reinterpret_cast<float4*>(&Vt[s]) = *reinterpret_cast<const float4*>(base + 128);
    }
    for (int i = tid; i < 125; i += 128) Bsh[i] = rpb[head * 125 + i];
    __syncthreads();

    const int lz = tid & 7, lw = (tid >> 3) & 3, lh = tid >> 5;
    const int qh = h0 + lh, qw = w0 + lw, qz = z0 + lz;
    const int n = (qh * 32 + qw) * 32 + qz;

    float q[16];
    {
        const float4* qp = reinterpret_cast<const float4*>(qkv + (size_t)n * 384 + head * 16);
        #pragma unroll
        for (int d4 = 0; d4 < 4; d4++) {
            float4 v = qp[d4];
            q[d4*4+0] = v.x * 0.25f; q[d4*4+1] = v.y * 0.25f;
            q[d4*4+2] = v.z * 0.25f; q[d4*4+3] = v.w * 0.25f;
        }
    }

    const int sh = min(max(qh - 1, 0), 29);
    const int sw = min(max(qw - 1, 0), 29);
    const int sz = min(max(qz - 1, 0), 29);

    float logits[27];
    float mx = -1e30f;
    #pragma unroll
    for (int ii = 0; ii < 27; ii++) {
        int iz = ii % 3, iw = (ii / 3) % 3, ih = ii / 9;
        int nh = sh + ih, nw_ = sw + iw, nz = sz + iz;
        int sp = ((nh - rbh) * 6 + (nw_ - rbw)) * 10 + (nz - rbz);
        float dot = 0.f;
        #pragma unroll
        for (int j = 0; j < 4; j++) {
            int s = (sp * 4 + (j ^ ((sp >> 1) & 3))) * 4;
            float4 kv = *reinterpret_cast<const float4*>(&Kt[s]);
            dot += q[j*4+0]*kv.x + q[j*4+1]*kv.y + q[j*4+2]*kv.z + q[j*4+3]*kv.w;
        }
        int rh = nh - qh + 2, rw = nw_ - qw + 2, rz = nz - qz + 2;
        dot += Bsh[(rh * 5 + rw) * 5 + rz];
        logits[ii] = dot;
        mx = fmaxf(mx, dot);
    }
    float s = 0.f;
    #pragma unroll
    for (int ii = 0; ii < 27; ii++) { logits[ii] = __expf(logits[ii] - mx); s += logits[ii]; }
    const float inv = 1.0f / s;

    float o[16] = {};
    #pragma unroll
    for (int ii = 0; ii < 27; ii++) {
        int iz = ii % 3, iw = (ii / 3) % 3, ih = ii / 9;
        int sp = ((sh + ih - rbh) * 6 + (sw + iw - rbw)) * 10 + (sz + iz - rbz);
        float w = logits[ii];
        #pragma unroll
        for (int j = 0; j < 4; j++) {
            int sidx = (sp * 4 + (j ^ ((sp >> 1) & 3))) * 4;
            float4 vv = *reinterpret_cast<const float4*>(&Vt[sidx]);
            o[j*4+0] += w * vv.x; o[j*4+1] += w * vv.y;
            o[j*4+2] += w * vv.z; o[j*4+3] += w * vv.w;
        }
    }
    float4* op = reinterpret_cast<float4*>(out + (size_t)n * 128 + head * 16);
    #pragma unroll
    for (int d4 = 0; d4 < 4; d4++) {
        float4 v;
        v.x = o[d4*4+0]*inv; v.y = o[d4*4+1]*inv;
        v.z = o[d4*4+2]*inv; v.w = o[d4*4+3]*inv;
        op[d4] = v;
    }
}

// ---------------------------------------------------------------------------
// Instance-norm stats (R9-proven): 256 blocks x 256 threads, float4 loads.
// ---------------------------------------------------------------------------
__global__ __launch_bounds__(256)
void stats_kernel(const float* __restrict__ y, float* __restrict__ part)
{
    __shared__ float sS[8][128];
    __shared__ float sS2[8][128];

    const int tid = threadIdx.x;
    const int c4  = (tid & 31) * 4;
    const int rg  = tid >> 5;
    const int r0  = blockIdx.x * 128;

    float s[4] = {}, s2[4] = {};
    #pragma unroll 16
    for (int r = rg; r < 128; r += 8) {
        float4 v = *reinterpret_cast<const float4*>(&y[(size_t)(r0 + r) * 128 + c4]);
        s[0] += v.x; s2[0] += v.x * v.x;
        s[1] += v.y; s2[1] += v.y * v.y;
        s[2] += v.z; s2[2] += v.z * v.z;
        s[3] += v.w; s2[3] += v.w * v.w;
    }
    #pragma unroll
    for (int e = 0; e < 4; e++) { sS[rg][c4 + e] = s[e]; sS2[rg][c4 + e] = s2[e]; }
    __syncthreads();
    if (tid < 128) {
        float ts = 0.f, ts2 = 0.f;
        #pragma unroll
        for (int g = 0; g < 8; g++) { ts += sS[g][tid]; ts2 += sS2[g][tid]; }
        part[blockIdx.x * 128 + tid] = ts;
        part[256 * 128 + blockIdx.x * 128 + tid] = ts2;
    }
}

__global__ void finalize_stats(const float* __restrict__ part, float* __restrict__ st)
{
    int c = threadIdx.x;
    float s = 0.f, s2 = 0.f;
    for (int b = 0; b < 256; b++) {
        s  += part[b * 128 + c];
        s2 += part[256 * 128 + b * 128 + c];
    }
    float m = s * (1.0f / NPOS);
    st[c] = m;
    st[128 + c] = rsqrtf(s2 * (1.0f / NPOS) - m * m + 1e-5f);
}

// ---------------------------------------------------------------------------
// Final: normalize + transpose [N,128] -> [128,N]
// ---------------------------------------------------------------------------
__global__ __launch_bounds__(256)
void transnorm(const float* __restrict__ y, const float* __restrict__ mean,
               const float* __restrict__ rstd, float* __restrict__ out)
{
    __shared__ float tile[32][33];
    const int n0 = blockIdx.x * 32;
    const int c0 = blockIdx.y * 32;
    const int tx = threadIdx.x, ty = threadIdx.y;
    for (int i = ty; i < 32; i += 8)
        tile[i][tx] = y[(size_t)(n0 + i) * 128 + c0 + tx];
    __syncthreads();
    for (int i = ty; i < 32; i += 8) {
        int c = c0 + i;
        out[(size_t)c * NPOS + n0 + tx] = (tile[tx][i] - mean[c]) * rstd[c];
    }
}

// ---------------------------------------------------------------------------
// Launch
// ---------------------------------------------------------------------------
extern "C" void kernel_launch(void* const* d_in, const int* in_sizes, int n_in,
                              void* d_out, int out_size)
{
    const float* x      = (const float*)d_in[0];
    const float* w_qkv  = (const float*)d_in[1];
    const float* b_qkv  = (const float*)d_in[2];
    const float* rpb    = (const float*)d_in[3];
    const float* w_proj = (const float*)d_in[4];
    const float* b_proj = (const float*)d_in[5];
    const float* w_ffn1 = (const float*)d_in[6];
    const float* b_ffn1 = (const float*)d_in[7];
    const float* w_ffn2 = (const float*)d_in[8];
    const float* b_ffn2 = (const float*)d_in[9];
    float* out = (float*)d_out;

    float *qkv, *attno, *proj, *ffn1, *y, *part, *st;
    cudaGetSymbolAddress((void**)&qkv,   g_qkv);
    cudaGetSymbolAddress((void**)&attno, g_attno);
    cudaGetSymbolAddress((void**)&proj,  g_proj);
    cudaGetSymbolAddress((void**)&ffn1,  g_ffn1);
    cudaGetSymbolAddress((void**)&y,     g_y);
    cudaGetSymbolAddress((void**)&part,  g_part);
    cudaGetSymbolAddress((void**)&st,    g_stats);

    // 1. QKV GEMM: A = x^T (x stored [128, N])
    mmagemm<true,false,false,false><<<dim3(3, 256), 256>>>(
        x, w_qkv, b_qkv, nullptr, nullptr, nullptr, qkv, NPOS, 384, 128);

    // 2. neighborhood attention
    nattn<<<dim3(256, NHEADS), 128>>>(qkv, rpb, attno);

    // 3. proj GEMM
    mmagemm<false,false,false,false><<<dim3(1, 256), 256>>>(
        attno, w_proj, b_proj, nullptr, nullptr, nullptr, proj, NPOS, 128, 128);

    // 4. instance norm #1 stats (of proj)
    stats_kernel<<<256, 256>>>(proj, part);
    finalize_stats<<<1, 128>>>(part, st);

    // 5. FFN1 (A = normalized proj) + gelu
    mmagemm<false,true,true,false><<<dim3(4, 256), 256>>>(
        proj, w_ffn1, b_ffn1, st, st + 128, nullptr, ffn1, NPOS, 512, 128);

    // 6. FFN2 + residual (residual = normalized proj)
    mmagemm<false,false,false,true><<<dim3(1, 256), 256>>>(
        ffn1, w_ffn2, b_ffn2, st, st + 128, proj, y, NPOS, 128, 512);

    // 7. instance norm #2 stats (of y)
    stats_kernel<<<256, 256>>>(y, part);
    finalize_stats<<<1, 128>>>(part, st);

    // 8. normalize + transpose to [C, N]
    transnorm<<<dim3(1024, 4), dim3(32, 8)>>>(y, st, st + 128, out);
}